// round 2
// baseline (speedup 1.0000x reference)
#include <cuda_runtime.h>

#define Bn   8
#define Cin  64
#define Hh   128
#define Ww   128
#define Cout 64
#define CIN2 66
#define KDIM 594   // CIN2 * 9
#define CHOM 27
#define TP   64    // pixels per block in dcn kernel

// ---------------- scratch (static device memory; no allocations) ----------------
__device__ float g_off [Bn*18*Hh*Ww];   // raw om channels 0..17
__device__ float g_mask[Bn*9*Hh*Ww];    // sigmoid(mask)
__device__ float g_wt  [KDIM*Cout];     // transposed main weight [k][o]

// ---------------- weight transpose prep ----------------
__global__ void prep_wt_kernel(const float* __restrict__ w)
{
    int i = blockIdx.x * 256 + threadIdx.x;
    if (i < Cout * KDIM) {
        int o = i / KDIM;
        int k = i - o * KDIM;
        g_wt[k * Cout + o] = w[i];
    }
}

// ---------------- Kernel A: offset/mask conv (27 out-channels, 66 in-channels, 3x3, pad 1) ----------------
// One block per (row y, batch b); 128 threads = one per output x.
__global__ void __launch_bounds__(128) om_conv_kernel(
    const float* __restrict__ input,
    const float* __restrict__ w_om,
    const float* __restrict__ b_om,
    float* __restrict__ idx_out,
    float* __restrict__ mask_out)
{
    extern __shared__ float sm[];
    float* sw   = sm;                 // KDIM * 28 floats
    float* rows = sm + KDIM * 28;     // 2 buffers * 3 rows * 132 floats

    const int tx = threadIdx.x;
    const int y  = blockIdx.x;
    const int b  = blockIdx.y;
    const float inv = 1.0f / 128.0f;

    // stage w_om into shared, transposed to [(c*9+t)][oc]
    for (int i = tx; i < CHOM * KDIM; i += 128) {
        int oc  = i / KDIM;
        int rem = i - oc * KDIM;        // rem = c*9 + t
        sw[rem * 28 + oc] = w_om[i];
    }

    float acc[28];
#pragma unroll
    for (int j = 0; j < 27; j++) acc[j] = b_om[j];
    acc[27] = 0.0f;

    // stage 3 input rows (cols -1..128, zero padded) of channel c into buffer buf
    auto stage = [&](int c, int buf) {
        float* dst = rows + buf * 396;
        for (int s = tx; s < 390; s += 128) {
            int r  = s / 130;
            int i  = s - r * 130;
            int yy = y + r - 1;
            int xx = i - 1;
            float val = 0.0f;
            if (yy >= 0 && yy < Hh && xx >= 0 && xx < Ww) {
                if (c < Cin)       val = input[(((b * Cin) + c) * Hh + yy) * Ww + xx];
                else if (c == Cin) val = yy * inv;            // h coordinate channel
                else               val = xx * inv - 0.5f;     // w coordinate channel
            }
            dst[r * 132 + i] = val;
        }
    };

    stage(0, 0);
    for (int c = 0; c < CIN2; c++) {
        __syncthreads();
        if (c + 1 < CIN2) stage(c + 1, (c + 1) & 1);
        const float* rb = rows + (c & 1) * 396;
        const float* wc = sw + c * 252;   // 9*28
#pragma unroll
        for (int t = 0; t < 9; t++) {
            float v = rb[(t / 3) * 132 + tx + (t % 3)];
            const float4* w4 = reinterpret_cast<const float4*>(wc + t * 28);
#pragma unroll
            for (int q = 0; q < 7; q++) {
                float4 wv = w4[q];
                acc[q * 4 + 0] += v * wv.x;
                acc[q * 4 + 1] += v * wv.y;
                acc[q * 4 + 2] += v * wv.z;
                acc[q * 4 + 3] += v * wv.w;
            }
        }
    }

    // emit offsets (scratch, om channel order), idx (output), mask (scratch + output)
    const int x = tx;
#pragma unroll
    for (int j = 0; j < 9; j++) {
        int o = ((b * 18 + j) * Hh + y) * Ww + x;
        g_off[o]   = acc[j];
        idx_out[o] = y * inv + (float)(j / 3 - 1) + acc[j];
    }
#pragma unroll
    for (int j = 0; j < 9; j++) {
        int o = ((b * 18 + 9 + j) * Hh + y) * Ww + x;
        g_off[o]   = acc[9 + j];
        idx_out[o] = x * inv - 0.5f + (float)(j % 3 - 1) + acc[9 + j];
    }
#pragma unroll
    for (int j = 0; j < 9; j++) {
        float s = 1.0f / (1.0f + __expf(-acc[18 + j]));
        int o = ((b * 9 + j) * Hh + y) * Ww + x;
        g_mask[o]   = s;
        mask_out[o] = s;
    }
}

// ---------------- Kernel B: deformable gather (im2col) + 64x594 GEMM ----------------
// Block = 64-pixel strip of one row. Shared: cols[594][64] + per-(tap,pixel) corner data.
// NOTE: tap t's (h,w) offsets are om channels (2t, 2t+1) — the reference's
// (18)->(9,2) reshape interleaves them.
__global__ void __launch_bounds__(256) dcn_kernel(
    const float* __restrict__ input,
    const float* __restrict__ bias,
    float* __restrict__ out)
{
    extern __shared__ float sm[];
    float*  cols = sm;                                   // [KDIM][TP]
    int4*   sIdx = (int4*)(sm + KDIM * TP);              // 9*TP entries
    float4* sWt  = (float4*)(sIdx + 9 * TP);             // 9*TP entries

    const int tid = threadIdx.x;
    const int x0  = blockIdx.x * TP;
    const int y   = blockIdx.y;
    const int b   = blockIdx.z;
    const float inv = 1.0f / 128.0f;

    // ---- phase 1a: per-(tap, pixel) bilinear corner data (+ analytic coord-channel cols) ----
    for (int q = tid; q < 9 * TP; q += 256) {
        int t = q / TP;
        int p = q - t * TP;
        int x = x0 + p;
        float oh = g_off [((b * 18 + 2 * t)     * Hh + y) * Ww + x];
        float ow = g_off [((b * 18 + 2 * t + 1) * Hh + y) * Ww + x];
        float mk = g_mask[((b * 9 + t)          * Hh + y) * Ww + x];

        float ph = oh + (float)(t / 3) + (float)(y - 1);
        float pw = ow + (float)(t % 3) + (float)(x - 1);
        float h0f = floorf(ph), w0f = floorf(pw);
        float lh = ph - h0f, lw = pw - w0f;
        float hh = 1.0f - lh, hw = 1.0f - lw;
        int h0 = (int)h0f, w0 = (int)w0f;
        int h1 = h0 + 1,   w1 = w0 + 1;
        float okh0 = (h0 >= 0 && h0 < Hh) ? 1.0f : 0.0f;
        float okh1 = (h1 >= 0 && h1 < Hh) ? 1.0f : 0.0f;
        float okw0 = (w0 >= 0 && w0 < Ww) ? 1.0f : 0.0f;
        float okw1 = (w1 >= 0 && w1 < Ww) ? 1.0f : 0.0f;
        float w00 = hh * hw * okh0 * okw0 * mk;
        float w01 = hh * lw * okh0 * okw1 * mk;
        float w10 = lh * hw * okh1 * okw0 * mk;
        float w11 = lh * lw * okh1 * okw1 * mk;
        int h0c = min(max(h0, 0), Hh - 1), h1c = min(max(h1, 0), Hh - 1);
        int w0c = min(max(w0, 0), Ww - 1), w1c = min(max(w1, 0), Ww - 1);

        sIdx[q] = make_int4(h0c * Ww, h1c * Ww, w0c, w1c);
        sWt[q]  = make_float4(w00, w01, w10, w11);

        // coordinate channels (c = 64, 65): analytic corner values
        cols[(Cin * 9 + t) * TP + p] =
            ((w00 + w01) * (float)h0c + (w10 + w11) * (float)h1c) * inv;
        cols[((Cin + 1) * 9 + t) * TP + p] =
            (w00 + w10) * ((float)w0c * inv - 0.5f) +
            (w01 + w11) * ((float)w1c * inv - 0.5f);
    }
    __syncthreads();

    // ---- phase 1b: gather 64 real channels into cols ----
    const float* binp = input + b * Cin * Hh * Ww;
    for (int e = tid; e < Cin * 9 * TP; e += 256) {
        int p = e & (TP - 1);
        int r = e >> 6;              // r = c*9 + t
        int t = r % 9;
        int c = r / 9;
        int q = t * TP + p;
        int4   id = sIdx[q];
        float4 wt = sWt[q];
        const float* pl = binp + c * (Hh * Ww);
        float v = wt.x * pl[id.x + id.z] + wt.y * pl[id.x + id.w]
                + wt.z * pl[id.y + id.z] + wt.w * pl[id.y + id.w];
        cols[r * TP + p] = v;
    }
    __syncthreads();

    // ---- phase 2: GEMM out[64][64px] = W[64][594] * cols[594][64px] ----
    const int og = tid >> 4;   // 0..15 -> 4 out channels each
    const int pg = tid & 15;   // 0..15 -> 4 pixels each
    float acc[4][4];
#pragma unroll
    for (int i = 0; i < 4; i++)
#pragma unroll
        for (int j = 0; j < 4; j++) acc[i][j] = 0.0f;

    const float* wbase = g_wt + og * 4;
    const float* cbase = cols + pg * 4;
#pragma unroll 6
    for (int k = 0; k < KDIM; k++) {
        float4 wv = __ldg(reinterpret_cast<const float4*>(wbase + k * Cout));
        float4 cv = *reinterpret_cast<const float4*>(cbase + k * TP);
        acc[0][0] += wv.x * cv.x; acc[0][1] += wv.x * cv.y;
        acc[0][2] += wv.x * cv.z; acc[0][3] += wv.x * cv.w;
        acc[1][0] += wv.y * cv.x; acc[1][1] += wv.y * cv.y;
        acc[1][2] += wv.y * cv.z; acc[1][3] += wv.y * cv.w;
        acc[2][0] += wv.z * cv.x; acc[2][1] += wv.z * cv.y;
        acc[2][2] += wv.z * cv.z; acc[2][3] += wv.z * cv.w;
        acc[3][0] += wv.w * cv.x; acc[3][1] += wv.w * cv.y;
        acc[3][2] += wv.w * cv.z; acc[3][3] += wv.w * cv.w;
    }

#pragma unroll
    for (int i = 0; i < 4; i++) {
        float bv = bias[og * 4 + i];
        float4 o;
        o.x = acc[i][0] + bv;
        o.y = acc[i][1] + bv;
        o.z = acc[i][2] + bv;
        o.w = acc[i][3] + bv;
        *reinterpret_cast<float4*>(
            out + ((b * Cout + og * 4 + i) * Hh + y) * Ww + x0 + pg * 4) = o;
    }
}

// ---------------- launcher ----------------
extern "C" void kernel_launch(void* const* d_in, const int* in_sizes, int n_in,
                              void* d_out, int out_size)
{
    const float* input  = (const float*)d_in[0];
    const float* weight = (const float*)d_in[1];
    const float* bias   = (const float*)d_in[2];
    const float* w_om   = (const float*)d_in[3];
    const float* b_om   = (const float*)d_in[4];

    float* out      = (float*)d_out;
    float* idx_out  = out + (size_t)Bn * Cout * Hh * Ww;            // 8,388,608
    float* mask_out = idx_out + (size_t)Bn * 18 * Hh * Ww;          // +2,359,296

    const int smA = (KDIM * 28 + 2 * 396) * 4;            // 69,696 B
    const int smB = (KDIM * TP) * 4 + 9 * TP * 16 * 2;    // 170,496 B
    cudaFuncSetAttribute(om_conv_kernel, cudaFuncAttributeMaxDynamicSharedMemorySize, smA);
    cudaFuncSetAttribute(dcn_kernel,     cudaFuncAttributeMaxDynamicSharedMemorySize, smB);

    prep_wt_kernel<<<(Cout * KDIM + 255) / 256, 256>>>(weight);
    om_conv_kernel<<<dim3(Hh, Bn), 128, smA>>>(input, w_om, b_om, idx_out, mask_out);
    dcn_kernel<<<dim3(Ww / TP, Hh, Bn), 256, smB>>>(input, bias, out);
}

// round 3
// speedup vs baseline: 1.9592x; 1.9592x over previous
#include <cuda_runtime.h>

#define Bn   8
#define Cin  64
#define Hh   128
#define Ww   128
#define Cout 64
#define CIN2 66
#define KDIM 594   // CIN2 * 9
#define CHOM 27
#define NCHUNK 33  // 2 channels per chunk; chunk 32 = coord channels (analytic)

// ---------------- scratch (static device memory; no allocations) ----------------
__device__ float g_off [Bn*18*Hh*Ww];   // raw om channels 0..17
__device__ float g_mask[Bn*9*Hh*Ww];    // sigmoid(mask)
__device__ float g_wt  [KDIM*Cout];     // transposed main weight [k][o]

// ---------------- weight transpose prep ----------------
__global__ void prep_wt_kernel(const float* __restrict__ w)
{
    int i = blockIdx.x * 256 + threadIdx.x;
    if (i < Cout * KDIM) {
        int o = i / KDIM;
        int k = i - o * KDIM;
        g_wt[k * Cout + o] = w[i];
    }
}

// ---------------- Kernel A: offset/mask conv (27 oc, 66 ic, 3x3, pad 1) ----------------
__global__ void __launch_bounds__(128) om_conv_kernel(
    const float* __restrict__ input,
    const float* __restrict__ w_om,
    const float* __restrict__ b_om,
    float* __restrict__ idx_out,
    float* __restrict__ mask_out)
{
    extern __shared__ float sm[];
    float* sw   = sm;                 // KDIM * 28 floats
    float* rows = sm + KDIM * 28;     // 2 buffers * 3 rows * 132 floats

    const int tx = threadIdx.x;
    const int y  = blockIdx.x;
    const int b  = blockIdx.y;
    const float inv = 1.0f / 128.0f;

    for (int i = tx; i < CHOM * KDIM; i += 128) {
        int oc  = i / KDIM;
        int rem = i - oc * KDIM;        // rem = c*9 + t
        sw[rem * 28 + oc] = w_om[i];
    }

    float acc[28];
#pragma unroll
    for (int j = 0; j < 27; j++) acc[j] = b_om[j];
    acc[27] = 0.0f;

    auto stage = [&](int c, int buf) {
        float* dst = rows + buf * 396;
        for (int s = tx; s < 390; s += 128) {
            int r  = s / 130;
            int i  = s - r * 130;
            int yy = y + r - 1;
            int xx = i - 1;
            float val = 0.0f;
            if (yy >= 0 && yy < Hh && xx >= 0 && xx < Ww) {
                if (c < Cin)       val = input[(((b * Cin) + c) * Hh + yy) * Ww + xx];
                else if (c == Cin) val = yy * inv;
                else               val = xx * inv - 0.5f;
            }
            dst[r * 132 + i] = val;
        }
    };

    stage(0, 0);
    for (int c = 0; c < CIN2; c++) {
        __syncthreads();
        if (c + 1 < CIN2) stage(c + 1, (c + 1) & 1);
        const float* rb = rows + (c & 1) * 396;
        const float* wc = sw + c * 252;
#pragma unroll
        for (int t = 0; t < 9; t++) {
            float v = rb[(t / 3) * 132 + tx + (t % 3)];
            const float4* w4 = reinterpret_cast<const float4*>(wc + t * 28);
#pragma unroll
            for (int q = 0; q < 7; q++) {
                float4 wv = w4[q];
                acc[q * 4 + 0] += v * wv.x;
                acc[q * 4 + 1] += v * wv.y;
                acc[q * 4 + 2] += v * wv.z;
                acc[q * 4 + 3] += v * wv.w;
            }
        }
    }

    const int x = tx;
#pragma unroll
    for (int j = 0; j < 9; j++) {
        int o = ((b * 18 + j) * Hh + y) * Ww + x;
        g_off[o]   = acc[j];
        idx_out[o] = y * inv + (float)(j / 3 - 1) + acc[j];
    }
#pragma unroll
    for (int j = 0; j < 9; j++) {
        int o = ((b * 18 + 9 + j) * Hh + y) * Ww + x;
        g_off[o]   = acc[9 + j];
        idx_out[o] = x * inv - 0.5f + (float)(j % 3 - 1) + acc[9 + j];
    }
#pragma unroll
    for (int j = 0; j < 9; j++) {
        float s = 1.0f / (1.0f + __expf(-acc[18 + j]));
        int o = ((b * 9 + j) * Hh + y) * Ww + x;
        g_mask[o]   = s;
        mask_out[o] = s;
    }
}

// ---------------- Kernel B: fused pipelined gather + GEMM ----------------
// Block = one full row (128 px), 256 threads, 3 blocks/SM.
// Double-buffered 2-channel chunks: gather chunk i+1 overlaps GEMM on chunk i.
// Tap t's (h,w) offsets are om channels (2t, 2t+1) [interleaving reshape].
__global__ void __launch_bounds__(256, 3) dcn_kernel(
    const float* __restrict__ input,
    const float* __restrict__ bias,
    float* __restrict__ out)
{
    extern __shared__ float sm[];
    int4*   sIdx = (int4*)sm;                       // [9*128]
    float4* sWt  = (float4*)(sm + 1152 * 4);        // [9*128]
    float*  cols = sm + 1152 * 8;                   // [2][18*128]

    const int tid = threadIdx.x;
    const int y   = blockIdx.x;
    const int b   = blockIdx.y;
    const float inv = 1.0f / 128.0f;

    // ---- phase 0: per-(tap, pixel) bilinear corner data ----
    for (int q = tid; q < 9 * 128; q += 256) {
        int t = q >> 7;
        int p = q & 127;
        float oh = g_off [((b * 18 + 2 * t)     * Hh + y) * Ww + p];
        float ow = g_off [((b * 18 + 2 * t + 1) * Hh + y) * Ww + p];
        float mk = g_mask[((b * 9 + t)          * Hh + y) * Ww + p];

        float ph = oh + (float)(t / 3) + (float)(y - 1);
        float pw = ow + (float)(t % 3) + (float)(p - 1);
        float h0f = floorf(ph), w0f = floorf(pw);
        float lh = ph - h0f, lw = pw - w0f;
        float hh = 1.0f - lh, hw = 1.0f - lw;
        int h0 = (int)h0f, w0 = (int)w0f;
        int h1 = h0 + 1,   w1 = w0 + 1;
        float okh0 = (h0 >= 0 && h0 < Hh) ? 1.0f : 0.0f;
        float okh1 = (h1 >= 0 && h1 < Hh) ? 1.0f : 0.0f;
        float okw0 = (w0 >= 0 && w0 < Ww) ? 1.0f : 0.0f;
        float okw1 = (w1 >= 0 && w1 < Ww) ? 1.0f : 0.0f;
        float w00 = hh * hw * okh0 * okw0 * mk;
        float w01 = hh * lw * okh0 * okw1 * mk;
        float w10 = lh * hw * okh1 * okw0 * mk;
        float w11 = lh * lw * okh1 * okw1 * mk;
        int h0c = min(max(h0, 0), Hh - 1), h1c = min(max(h1, 0), Hh - 1);
        int w0c = min(max(w0, 0), Ww - 1), w1c = min(max(w1, 0), Ww - 1);

        sIdx[q] = make_int4(h0c * Ww, h1c * Ww, w0c, w1c);
        sWt[q]  = make_float4(w00, w01, w10, w11);
    }
    __syncthreads();

    const float* binp = input + b * Cin * Hh * Ww;

    // gather one 2-channel chunk into registers (9 items/thread; 2304 = 9*256)
    float vals[9];
    auto gather = [&](int cn) {
#pragma unroll
        for (int j = 0; j < 9; j++) {
            int e = j * 256 + tid;
            int p = e & 127;
            int r = e >> 7;            // r = c2*9 + t, r in 0..17
            int c2 = (r >= 9);
            int t  = r - c2 * 9;
            int q  = t * 128 + p;
            int4   id = sIdx[q];
            float4 wt = sWt[q];
            if (cn < 32) {
                const float* pl = binp + (2 * cn + c2) * (Hh * Ww);
                vals[j] = wt.x * pl[id.x + id.z] + wt.y * pl[id.x + id.w]
                        + wt.z * pl[id.y + id.z] + wt.w * pl[id.y + id.w];
            } else if (c2 == 0) {   // h-coordinate channel (64)
                vals[j] = ((wt.x + wt.y) * (float)(id.x >> 7)
                         + (wt.z + wt.w) * (float)(id.y >> 7)) * inv;
            } else {                // w-coordinate channel (65)
                vals[j] = (wt.x + wt.z) * ((float)id.z * inv - 0.5f)
                        + (wt.y + wt.w) * ((float)id.w * inv - 0.5f);
            }
        }
    };
    auto store_vals = [&](int buf) {
        float* dst = cols + buf * (18 * 128);
#pragma unroll
        for (int j = 0; j < 9; j++) {
            int e = j * 256 + tid;
            dst[(e >> 7) * 128 + (e & 127)] = vals[j];
        }
    };

    // thread tile: 4 out-channels x 8 pixels
    const int og = tid >> 4;   // 0..15
    const int pg = tid & 15;   // 0..15
    float acc[4][8];
#pragma unroll
    for (int i = 0; i < 4; i++)
#pragma unroll
        for (int j = 0; j < 8; j++) acc[i][j] = 0.0f;

    gather(0);
    store_vals(0);
    __syncthreads();

    for (int c = 0; c < NCHUNK; c++) {
        if (c + 1 < NCHUNK) gather(c + 1);   // LDGs in flight during GEMM

        const float* cb = cols + (c & 1) * (18 * 128) + pg * 8;
        const float* wb = g_wt + (c * 18) * Cout + og * 4;
#pragma unroll
        for (int kk = 0; kk < 18; kk++) {
            float4 wv  = __ldg(reinterpret_cast<const float4*>(wb + kk * Cout));
            float4 cv0 = *reinterpret_cast<const float4*>(cb + kk * 128);
            float4 cv1 = *reinterpret_cast<const float4*>(cb + kk * 128 + 4);
#pragma unroll
            for (int i = 0; i < 4; i++) {
                float w = (i == 0) ? wv.x : (i == 1) ? wv.y : (i == 2) ? wv.z : wv.w;
                acc[i][0] += w * cv0.x; acc[i][1] += w * cv0.y;
                acc[i][2] += w * cv0.z; acc[i][3] += w * cv0.w;
                acc[i][4] += w * cv1.x; acc[i][5] += w * cv1.y;
                acc[i][6] += w * cv1.z; acc[i][7] += w * cv1.w;
            }
        }

        if (c + 1 < NCHUNK) {
            store_vals((c + 1) & 1);
            __syncthreads();
        }
    }

#pragma unroll
    for (int i = 0; i < 4; i++) {
        float bv = bias[og * 4 + i];
        float* op = out + ((b * Cout + og * 4 + i) * Hh + y) * Ww + pg * 8;
        float4 o0 = make_float4(acc[i][0] + bv, acc[i][1] + bv, acc[i][2] + bv, acc[i][3] + bv);
        float4 o1 = make_float4(acc[i][4] + bv, acc[i][5] + bv, acc[i][6] + bv, acc[i][7] + bv);
        *reinterpret_cast<float4*>(op)     = o0;
        *reinterpret_cast<float4*>(op + 4) = o1;
    }
}

// ---------------- launcher ----------------
extern "C" void kernel_launch(void* const* d_in, const int* in_sizes, int n_in,
                              void* d_out, int out_size)
{
    const float* input  = (const float*)d_in[0];
    const float* weight = (const float*)d_in[1];
    const float* bias   = (const float*)d_in[2];
    const float* w_om   = (const float*)d_in[3];
    const float* b_om   = (const float*)d_in[4];

    float* out      = (float*)d_out;
    float* idx_out  = out + (size_t)Bn * Cout * Hh * Ww;
    float* mask_out = idx_out + (size_t)Bn * 18 * Hh * Ww;

    const int smA = (KDIM * 28 + 2 * 396) * 4;                 // 69,696 B
    const int smB = (1152 * 8 + 2 * 18 * 128) * 4;             // 55,296 B
    cudaFuncSetAttribute(om_conv_kernel, cudaFuncAttributeMaxDynamicSharedMemorySize, smA);
    cudaFuncSetAttribute(dcn_kernel,     cudaFuncAttributeMaxDynamicSharedMemorySize, smB);

    prep_wt_kernel<<<(Cout * KDIM + 255) / 256, 256>>>(weight);
    om_conv_kernel<<<dim3(Hh, Bn), 128, smA>>>(input, w_om, b_om, idx_out, mask_out);
    dcn_kernel<<<dim3(Hh, Bn), 256, smB>>>(input, bias, out);
}

// round 4
// speedup vs baseline: 2.3343x; 1.1915x over previous
#include <cuda_runtime.h>

#define Bn   8
#define Cin  64
#define Hh   128
#define Ww   128
#define HW   (Hh*Ww)
#define Cout 64
#define CIN2 66
#define KDIM 594   // CIN2 * 9
#define CHOM 27
#define NCHUNK 33  // 2 channels per chunk; chunk 32 = coord channels (analytic)

// ---------------- scratch (static device memory; no allocations) ----------------
__device__ float g_off [Bn*18*Hh*Ww];   // raw om channels 0..17
__device__ float g_mask[Bn*9*Hh*Ww];    // sigmoid(mask)
__device__ float g_wt  [KDIM*Cout];     // transposed main weight [k][o]

// ---------------- weight transpose prep ----------------
__global__ void prep_wt_kernel(const float* __restrict__ w)
{
    int i = blockIdx.x * 256 + threadIdx.x;
    if (i < Cout * KDIM) {
        int o = i / KDIM;
        int k = i - o * KDIM;
        g_wt[k * Cout + o] = w[i];
    }
}

// ---------------- Kernel A: offset/mask conv (27 oc, 66 ic, 3x3, pad 1) ----------------
__global__ void __launch_bounds__(128) om_conv_kernel(
    const float* __restrict__ input,
    const float* __restrict__ w_om,
    const float* __restrict__ b_om,
    float* __restrict__ idx_out,
    float* __restrict__ mask_out)
{
    extern __shared__ float sm[];
    float* sw   = sm;                 // KDIM * 28 floats
    float* rows = sm + KDIM * 28;     // 2 buffers * 3 rows * 132 floats

    const int tx = threadIdx.x;
    const int y  = blockIdx.x;
    const int b  = blockIdx.y;
    const float inv = 1.0f / 128.0f;

    for (int i = tx; i < CHOM * KDIM; i += 128) {
        int oc  = i / KDIM;
        int rem = i - oc * KDIM;        // rem = c*9 + t
        sw[rem * 28 + oc] = w_om[i];
    }

    float acc[28];
#pragma unroll
    for (int j = 0; j < 27; j++) acc[j] = b_om[j];
    acc[27] = 0.0f;

    auto stage = [&](int c, int buf) {
        float* dst = rows + buf * 396;
        for (int s = tx; s < 390; s += 128) {
            int r  = s / 130;
            int i  = s - r * 130;
            int yy = y + r - 1;
            int xx = i - 1;
            float val = 0.0f;
            if (yy >= 0 && yy < Hh && xx >= 0 && xx < Ww) {
                if (c < Cin)       val = input[(((b * Cin) + c) * Hh + yy) * Ww + xx];
                else if (c == Cin) val = yy * inv;
                else               val = xx * inv - 0.5f;
            }
            dst[r * 132 + i] = val;
        }
    };

    stage(0, 0);
    for (int c = 0; c < CIN2; c++) {
        __syncthreads();
        if (c + 1 < CIN2) stage(c + 1, (c + 1) & 1);
        const float* rb = rows + (c & 1) * 396;
        const float* wc = sw + c * 252;
#pragma unroll
        for (int t = 0; t < 9; t++) {
            float v = rb[(t / 3) * 132 + tx + (t % 3)];
            const float4* w4 = reinterpret_cast<const float4*>(wc + t * 28);
#pragma unroll
            for (int q = 0; q < 7; q++) {
                float4 wv = w4[q];
                acc[q * 4 + 0] += v * wv.x;
                acc[q * 4 + 1] += v * wv.y;
                acc[q * 4 + 2] += v * wv.z;
                acc[q * 4 + 3] += v * wv.w;
            }
        }
    }

    const int x = tx;
#pragma unroll
    for (int j = 0; j < 9; j++) {
        int o = ((b * 18 + j) * Hh + y) * Ww + x;
        g_off[o]   = acc[j];
        idx_out[o] = y * inv + (float)(j / 3 - 1) + acc[j];
    }
#pragma unroll
    for (int j = 0; j < 9; j++) {
        int o = ((b * 18 + 9 + j) * Hh + y) * Ww + x;
        g_off[o]   = acc[9 + j];
        idx_out[o] = x * inv - 0.5f + (float)(j % 3 - 1) + acc[9 + j];
    }
#pragma unroll
    for (int j = 0; j < 9; j++) {
        float s = 1.0f / (1.0f + __expf(-acc[18 + j]));
        int o = ((b * 9 + j) * Hh + y) * Ww + x;
        g_mask[o]   = s;
        mask_out[o] = s;
    }
}

// ---------------- Kernel B: warp-specialized gather + GEMM ----------------
// 384 threads: tid 0..255 = consumers (GEMM), tid 256..383 = producers (gather).
// Double-buffered 2-channel chunks; producers fill chunk c+1 while consumers
// run GEMM on chunk c. Tap t's (h,w) offsets are om channels (2t, 2t+1).
__global__ void __launch_bounds__(384, 2) dcn_kernel(
    const float* __restrict__ input,
    const float* __restrict__ bias,
    float* __restrict__ out)
{
    extern __shared__ float sm[];
    int4*   sIdx = (int4*)sm;                       // [9*128]
    float4* sWt  = (float4*)(sm + 1152 * 4);        // [9*128]
    float*  cols = sm + 1152 * 8;                   // [2][18*128]

    const int tid = threadIdx.x;
    const int y   = blockIdx.x;
    const int b   = blockIdx.y;
    const float inv = 1.0f / 128.0f;

    // ---- phase 0 (all threads): per-(tap, pixel) bilinear corner data ----
    for (int q = tid; q < 9 * 128; q += 384) {
        int t = q >> 7;
        int p = q & 127;
        float oh = g_off [((b * 18 + 2 * t)     * Hh + y) * Ww + p];
        float ow = g_off [((b * 18 + 2 * t + 1) * Hh + y) * Ww + p];
        float mk = g_mask[((b * 9 + t)          * Hh + y) * Ww + p];

        float ph = oh + (float)(t / 3) + (float)(y - 1);
        float pw = ow + (float)(t % 3) + (float)(p - 1);
        float h0f = floorf(ph), w0f = floorf(pw);
        float lh = ph - h0f, lw = pw - w0f;
        float hh = 1.0f - lh, hw = 1.0f - lw;
        int h0 = (int)h0f, w0 = (int)w0f;
        int h1 = h0 + 1,   w1 = w0 + 1;
        float okh0 = (h0 >= 0 && h0 < Hh) ? 1.0f : 0.0f;
        float okh1 = (h1 >= 0 && h1 < Hh) ? 1.0f : 0.0f;
        float okw0 = (w0 >= 0 && w0 < Ww) ? 1.0f : 0.0f;
        float okw1 = (w1 >= 0 && w1 < Ww) ? 1.0f : 0.0f;
        float w00 = hh * hw * okh0 * okw0 * mk;
        float w01 = hh * lw * okh0 * okw1 * mk;
        float w10 = lh * hw * okh1 * okw0 * mk;
        float w11 = lh * lw * okh1 * okw1 * mk;
        int h0c = min(max(h0, 0), Hh - 1), h1c = min(max(h1, 0), Hh - 1);
        int w0c = min(max(w0, 0), Ww - 1), w1c = min(max(w1, 0), Ww - 1);

        sIdx[q] = make_int4(h0c * Ww, h1c * Ww, w0c, w1c);
        sWt[q]  = make_float4(w00, w01, w10, w11);
    }
    __syncthreads();

    const float* binp = input + b * Cin * HW;

    if (tid >= 256) {
        // ================= PRODUCER (warps 8-11) =================
        const int ptid = tid - 256;   // 0..127 : one pixel per thread

        auto produce = [&](int cn, int buf) {
            float* dst = cols + buf * 2304 + ptid;
            if (cn < 32) {
                const float* pl0 = binp + (2 * cn) * HW;
                const float* pl1 = pl0 + HW;
#pragma unroll
                for (int t = 0; t < 9; t++) {
                    int q = t * 128 + ptid;
                    int4   id = sIdx[q];
                    float4 wt = sWt[q];
                    int a00 = id.x + id.z, a01 = id.x + id.w;
                    int a10 = id.y + id.z, a11 = id.y + id.w;
                    float v0 = wt.x * pl0[a00] + wt.y * pl0[a01]
                             + wt.z * pl0[a10] + wt.w * pl0[a11];
                    float v1 = wt.x * pl1[a00] + wt.y * pl1[a01]
                             + wt.z * pl1[a10] + wt.w * pl1[a11];
                    dst[t * 128]       = v0;
                    dst[(9 + t) * 128] = v1;
                }
            } else {
#pragma unroll
                for (int t = 0; t < 9; t++) {
                    int q = t * 128 + ptid;
                    int4   id = sIdx[q];
                    float4 wt = sWt[q];
                    dst[t * 128] = ((wt.x + wt.y) * (float)(id.x >> 7)
                                  + (wt.z + wt.w) * (float)(id.y >> 7)) * inv;
                    dst[(9 + t) * 128] =
                          (wt.x + wt.z) * ((float)id.z * inv - 0.5f)
                        + (wt.y + wt.w) * ((float)id.w * inv - 0.5f);
                }
            }
        };

        produce(0, 0);
        __syncthreads();
        for (int c = 0; c < NCHUNK; c++) {
            if (c + 1 < NCHUNK) produce(c + 1, (c + 1) & 1);
            __syncthreads();
        }
    } else {
        // ================= CONSUMER (warps 0-7): GEMM =================
        const int og = tid >> 4;   // 0..15 -> 4 out channels
        const int pg = tid & 15;   // 0..15 -> 8 pixels
        float acc[4][8];
#pragma unroll
        for (int i = 0; i < 4; i++)
#pragma unroll
            for (int j = 0; j < 8; j++) acc[i][j] = 0.0f;

        __syncthreads();   // matches producer's post-produce(0) barrier
        for (int c = 0; c < NCHUNK; c++) {
            const float* cb = cols + (c & 1) * 2304 + pg * 8;
            const float* wb = g_wt + (c * 18) * Cout + og * 4;
#pragma unroll 6
            for (int kk = 0; kk < 18; kk++) {
                float4 wv  = __ldg(reinterpret_cast<const float4*>(wb + kk * Cout));
                float4 cv0 = *reinterpret_cast<const float4*>(cb + kk * 128);
                float4 cv1 = *reinterpret_cast<const float4*>(cb + kk * 128 + 4);
#pragma unroll
                for (int i = 0; i < 4; i++) {
                    float w = (i == 0) ? wv.x : (i == 1) ? wv.y : (i == 2) ? wv.z : wv.w;
                    acc[i][0] += w * cv0.x; acc[i][1] += w * cv0.y;
                    acc[i][2] += w * cv0.z; acc[i][3] += w * cv0.w;
                    acc[i][4] += w * cv1.x; acc[i][5] += w * cv1.y;
                    acc[i][6] += w * cv1.z; acc[i][7] += w * cv1.w;
                }
            }
            __syncthreads();
        }

#pragma unroll
        for (int i = 0; i < 4; i++) {
            float bv = bias[og * 4 + i];
            float* op = out + ((b * Cout + og * 4 + i) * Hh + y) * Ww + pg * 8;
            float4 o0 = make_float4(acc[i][0] + bv, acc[i][1] + bv,
                                    acc[i][2] + bv, acc[i][3] + bv);
            float4 o1 = make_float4(acc[i][4] + bv, acc[i][5] + bv,
                                    acc[i][6] + bv, acc[i][7] + bv);
            *reinterpret_cast<float4*>(op)     = o0;
            *reinterpret_cast<float4*>(op + 4) = o1;
        }
    }
}

// ---------------- launcher ----------------
extern "C" void kernel_launch(void* const* d_in, const int* in_sizes, int n_in,
                              void* d_out, int out_size)
{
    const float* input  = (const float*)d_in[0];
    const float* weight = (const float*)d_in[1];
    const float* bias   = (const float*)d_in[2];
    const float* w_om   = (const float*)d_in[3];
    const float* b_om   = (const float*)d_in[4];

    float* out      = (float*)d_out;
    float* idx_out  = out + (size_t)Bn * Cout * Hh * Ww;
    float* mask_out = idx_out + (size_t)Bn * 18 * Hh * Ww;

    const int smA = (KDIM * 28 + 2 * 396) * 4;                 // 69,696 B
    const int smB = (1152 * 8 + 2 * 2304) * 4;                 // 55,296 B
    cudaFuncSetAttribute(om_conv_kernel, cudaFuncAttributeMaxDynamicSharedMemorySize, smA);
    cudaFuncSetAttribute(dcn_kernel,     cudaFuncAttributeMaxDynamicSharedMemorySize, smB);

    prep_wt_kernel<<<(Cout * KDIM + 255) / 256, 256>>>(weight);
    om_conv_kernel<<<dim3(Hh, Bn), 128, smA>>>(input, w_om, b_om, idx_out, mask_out);
    dcn_kernel<<<dim3(Hh, Bn), 384, smB>>>(input, bias, out);
}